// round 2
// baseline (speedup 1.0000x reference)
#include <cuda_runtime.h>

#define DTV      0.02f
#define SQRT_DT  0.141421356237309515f
#define SIGMA    0.5f
#define NSTEP    50
#define BATCH    4096
#define PPC      32            // paths per CTA
#define NCTA     (BATCH / PPC) // 128
#define NTHR     128

typedef unsigned long long u64;

// ---- shared-memory layout (float offsets) ----
// per-net scalar block:
#define W_IN   0       // [2][64] = 128
#define B_IN   128     // 64
#define W_H    192     // [3][64][64] = 12288
#define B_H    12480   // [3][64] = 192
#define W_OUT  12672   // 64
#define B_OUT  12736   // 1 (+3 pad)
#define NET_SZ 12740
// activations: duplicated pairs {x,x}, layout [64 rows][32 u64], XOR-swizzled
// row = hidden unit j (or input unit), column u64 = path p (dup'd float2)
#define XBUF     4096                 // floats per buffer (64*32*2)
#define OFF_X    (2 * NET_SZ)         // 25480 (16B aligned: *4 = 101920)
#define OFF_DX   (OFF_X  + XBUF)
#define OFF_XN   (OFF_DX + XBUF)
#define OFF_DXN  (OFF_XN + XBUF)
#define OFF_YS   (OFF_DXN + XBUF)
#define SMEM_FLOATS (OFF_YS + 32)
#define SMEM_BYTES  (SMEM_FLOATS * 4)

__device__ float g_part[NCTA];

__global__ void k_fin(float* out) {
    // deterministic reduction of per-CTA partials
    __shared__ float sh[NTHR];
    float v = g_part[threadIdx.x];
    sh[threadIdx.x] = v;
    __syncthreads();
    if (threadIdx.x == 0) {
        float acc = 0.0f;
        for (int i = 0; i < NCTA; i++) acc += sh[i];
        out[0] = acc * (1.0f / (float)BATCH);
    }
}

__device__ __forceinline__ void cpf(float* d, const float* s, int n, int tid) {
    for (int i = tid; i < n; i += NTHR) d[i] = s[i];
}

__device__ __forceinline__ u64 fma2(u64 a, u64 b, u64 c) {
    u64 d;
    asm("fma.rn.f32x2 %0, %1, %2, %3;" : "=l"(d) : "l"(a), "l"(b), "l"(c));
    return d;
}
__device__ __forceinline__ u64 pk(float lo, float hi) {
    u64 r;
    asm("mov.b64 %0, {%1, %2};" : "=l"(r) : "f"(lo), "f"(hi));
    return r;
}
__device__ __forceinline__ void upk(u64 v, float& lo, float& hi) {
    asm("mov.b64 {%0, %1}, %2;" : "=f"(lo), "=f"(hi) : "l"(v));
}

// swizzled 16B-chunk index within a 64-row x 256B activation buffer
// logical chunk c (0..15, = path_pair index), row r: phys = c ^ ((r>>2)&15)
__device__ __forceinline__ int swz(int c, int r) { return c ^ ((r >> 2) & 15); }

// One hidden layer, accumulators packed over j-pairs via fma.rn.f32x2.
// Xn[j][p] = sin( sum_i X[i][p] * W[i][j] + b[j] )
// (TANG) dXn[j][p] = cos(a) * sum_i dX[i][p] * W[i][j]
template <bool TANG>
__device__ __forceinline__ void hidden_layer(
    const float* __restrict__ W, const float* __restrict__ b,
    const float* __restrict__ X, const float* __restrict__ dXb,
    float* __restrict__ Xn, float* __restrict__ dXn,
    int jg, int pg)
{
    const ulonglong2* W2  = (const ulonglong2*)W;    // 16 ull2 per 64-float row
    const ulonglong2* X2  = (const ulonglong2*)X;    // 16 ull2 per row
    const ulonglong2* dX2 = (const ulonglong2*)dXb;

    const int j0 = jg * 4;

    u64 ah[2][4], ad[2][4];
    {
        u64 b01 = pk(b[j0], b[j0 + 1]);
        u64 b23 = pk(b[j0 + 2], b[j0 + 3]);
#pragma unroll
        for (int p = 0; p < 4; p++) {
            ah[0][p] = b01; ah[1][p] = b23;
            ad[0][p] = 0ull; ad[1][p] = 0ull;
        }
    }

#pragma unroll 8
    for (int i = 0; i < 64; i++) {
        ulonglong2 w = W2[i * 16 + jg];          // {wj0,wj1},{wj2,wj3}
        int c0 = swz(pg * 2, i);
        int c1 = swz(pg * 2 + 1, i);
        ulonglong2 xa = X2[i * 16 + c0];         // {xp0,xp0},{xp1,xp1}
        ulonglong2 xb = X2[i * 16 + c1];         // {xp2,xp2},{xp3,xp3}
        u64 xd[4] = {xa.x, xa.y, xb.x, xb.y};
#pragma unroll
        for (int p = 0; p < 4; p++) {
            ah[0][p] = fma2(w.x, xd[p], ah[0][p]);
            ah[1][p] = fma2(w.y, xd[p], ah[1][p]);
        }
        if (TANG) {
            ulonglong2 da = dX2[i * 16 + c0];
            ulonglong2 db = dX2[i * 16 + c1];
            u64 dd[4] = {da.x, da.y, db.x, db.y};
#pragma unroll
            for (int p = 0; p < 4; p++) {
                ad[0][p] = fma2(w.x, dd[p], ad[0][p]);
                ad[1][p] = fma2(w.y, dd[p], ad[1][p]);
            }
        }
    }

    // unpack, activate, store dup'd + swizzled
    float hv[4][4], dv[4][4];
#pragma unroll
    for (int p = 0; p < 4; p++) {
        upk(ah[0][p], hv[0][p], hv[1][p]);
        upk(ah[1][p], hv[2][p], hv[3][p]);
        if (TANG) {
            upk(ad[0][p], dv[0][p], dv[1][p]);
            upk(ad[1][p], dv[2][p], dv[3][p]);
        }
    }

    ulonglong2* Xn2  = (ulonglong2*)Xn;
    ulonglong2* dXn2 = (ulonglong2*)dXn;
#pragma unroll
    for (int jj = 0; jj < 4; jj++) {
        int r = j0 + jj;
        float s[4], c[4];
#pragma unroll
        for (int p = 0; p < 4; p++) __sincosf(hv[jj][p], &s[p], &c[p]);
        int cc0 = swz(pg * 2, r);
        int cc1 = swz(pg * 2 + 1, r);
        Xn2[r * 16 + cc0] = make_ulonglong2(pk(s[0], s[0]), pk(s[1], s[1]));
        Xn2[r * 16 + cc1] = make_ulonglong2(pk(s[2], s[2]), pk(s[3], s[3]));
        if (TANG) {
            float d0 = c[0] * dv[jj][0], d1 = c[1] * dv[jj][1];
            float d2 = c[2] * dv[jj][2], d3 = c[3] * dv[jj][3];
            dXn2[r * 16 + cc0] = make_ulonglong2(pk(d0, d0), pk(d1, d1));
            dXn2[r * 16 + cc1] = make_ulonglong2(pk(d2, d2), pk(d3, d3));
        }
    }
}

// Full net evaluation at time tval on state ys[] (in smem).
// If TANG: also propagates the tangent d/dy and returns doutv.
// outv/doutv valid only for tid < 32 (thread p owns path p).
template <bool TANG>
__device__ __forceinline__ void eval_net(
    const float* __restrict__ net, float* __restrict__ sm, float tval,
    int jg, int pg, int tid, float& outv, float& doutv)
{
    float* X   = sm + OFF_X;
    float* dXb = sm + OFF_DX;
    float* Xn  = sm + OFF_XN;
    float* dXn = sm + OFF_DXN;
    const float* ys = sm + OFF_YS;

    const int j0 = jg * 4, p0 = pg * 4;

    // ---- input layer: sin(t*wt + y*wy + b), tangent wrt y: cos * wy ----
    ulonglong2* X2  = (ulonglong2*)X;
    ulonglong2* dX2 = (ulonglong2*)dXb;
    float yv[4] = {ys[p0], ys[p0 + 1], ys[p0 + 2], ys[p0 + 3]};
#pragma unroll
    for (int jj = 0; jj < 4; jj++) {
        int r = j0 + jj;
        float wt = net[W_IN + r];
        float wy = net[W_IN + 64 + r];
        float bj = net[B_IN + r];
        float tb = fmaf(tval, wt, bj);
        float s[4], c[4];
#pragma unroll
        for (int p = 0; p < 4; p++) {
            float a = fmaf(yv[p], wy, tb);
            __sincosf(a, &s[p], &c[p]);
        }
        int cc0 = swz(pg * 2, r);
        int cc1 = swz(pg * 2 + 1, r);
        X2[r * 16 + cc0] = make_ulonglong2(pk(s[0], s[0]), pk(s[1], s[1]));
        X2[r * 16 + cc1] = make_ulonglong2(pk(s[2], s[2]), pk(s[3], s[3]));
        if (TANG) {
            float d0 = c[0] * wy, d1 = c[1] * wy, d2 = c[2] * wy, d3 = c[3] * wy;
            dX2[r * 16 + cc0] = make_ulonglong2(pk(d0, d0), pk(d1, d1));
            dX2[r * 16 + cc1] = make_ulonglong2(pk(d2, d2), pk(d3, d3));
        }
    }
    __syncthreads();
    hidden_layer<TANG>(net + W_H,        net + B_H,       X,  dXb, Xn, dXn, jg, pg);
    __syncthreads();
    hidden_layer<TANG>(net + W_H + 4096, net + B_H + 64,  Xn, dXn, X,  dXb, jg, pg);
    __syncthreads();
    hidden_layer<TANG>(net + W_H + 8192, net + B_H + 128, X,  dXb, Xn, dXn, jg, pg);
    __syncthreads();

    // ---- output layer: 32 threads, one path each ----
    if (tid < 32) {
        int p = tid;
        float acc  = net[B_OUT];
        float dacc = 0.0f;
#pragma unroll 8
        for (int i = 0; i < 64; i++) {
            int ch = swz(p >> 1, i);
            int off = i * 64 + ch * 4 + (p & 1) * 2;   // lo float of the dup pair
            float w = net[W_OUT + i];
            acc = fmaf(Xn[off], w, acc);
            if (TANG) dacc = fmaf(dXn[off], w, dacc);
        }
        outv  = acc;
        doutv = dacc;
    }
}

__global__ __launch_bounds__(NTHR, 1) void fbsnn_main(
    const float* __restrict__ yWin,  const float* __restrict__ yBin,
    const float* __restrict__ yWh,   const float* __restrict__ yBh,
    const float* __restrict__ yWout, const float* __restrict__ yBout,
    const float* __restrict__ qWin,  const float* __restrict__ qBin,
    const float* __restrict__ qWh,   const float* __restrict__ qBh,
    const float* __restrict__ qWout, const float* __restrict__ qBout,
    const float* __restrict__ y0,    const float* __restrict__ dW)
{
    extern __shared__ float sm[];
    const int tid = threadIdx.x;
    const int jg = tid & 15;   // 16 groups of 4 output neurons
    const int pg = tid >> 4;   // 8 groups of 4 paths

    // ---- stage all weights into smem once ----
    cpf(sm + W_IN,  yWin, 128,   tid);
    cpf(sm + B_IN,  yBin, 64,    tid);
    cpf(sm + W_H,   yWh,  12288, tid);
    cpf(sm + B_H,   yBh,  192,   tid);
    cpf(sm + W_OUT, yWout, 64,   tid);
    if (tid == 0) sm[B_OUT] = yBout[0];
    float* smq = sm + NET_SZ;
    cpf(smq + W_IN,  qWin, 128,   tid);
    cpf(smq + B_IN,  qBin, 64,    tid);
    cpf(smq + W_H,   qWh,  12288, tid);
    cpf(smq + B_H,   qBh,  192,   tid);
    cpf(smq + W_OUT, qWout, 64,   tid);
    if (tid == 0) smq[B_OUT] = qBout[0];
    if (tid < 32) sm[OFF_YS + tid] = y0[0];
    __syncthreads();

    float Yv = 0.0f, dYv = 0.0f, lossAcc = 0.0f, Ytilde = 0.0f;

    // initial Y_and_grad at t = 0
    eval_net<true>(sm, sm, 0.0f, jg, pg, tid, Yv, dYv);
    __syncthreads();

    const int pbase = blockIdx.x * PPC;

    for (int n = 0; n < NSTEP; n++) {
        float t = (float)n * DTV;

        // q = q_net(t, y)
        float qv = 0.0f, qd_dummy = 0.0f;
        eval_net<false>(smq, sm, t, jg, pg, tid, qv, qd_dummy);
        __syncthreads();

        if (tid < 32) {
            float dwn = SQRT_DT * dW[n * BATCH + pbase + tid];
            float y1  = sm[OFF_YS + tid] + qv * DTV + SIGMA * dwn;
            // Y1_tilde = Y - q^2*dt + (sigma*dY)*dWn
            Ytilde = Yv - qv * qv * DTV + SIGMA * dYv * dwn;
            sm[OFF_YS + tid] = y1;
        }
        __syncthreads();

        // Y1, dY1 at (t+dt, y1)
        eval_net<true>(sm, sm, t + DTV, jg, pg, tid, Yv, dYv);
        __syncthreads();

        if (tid < 32) {
            float e = Yv - Ytilde;
            lossAcc = fmaf(e, e, lossAcc);
        }
    }

    if (tid < 32) {
        float yN = sm[OFF_YS + tid];
        float e1 = Yv - yN * yN;       // terminal value residual
        float e2 = dYv - 2.0f * yN;    // terminal gradient residual
        lossAcc = fmaf(e1, e1, fmaf(e2, e2, lossAcc));
#pragma unroll
        for (int o = 16; o > 0; o >>= 1)
            lossAcc += __shfl_down_sync(0xffffffffu, lossAcc, o);
        if (tid == 0) g_part[blockIdx.x] = lossAcc;
    }
}

extern "C" void kernel_launch(void* const* d_in, const int* in_sizes, int n_in,
                              void* d_out, int out_size)
{
    const float *yWin, *yBin, *yWh, *yBh, *yWout, *yBout;
    const float *qWin, *qBin, *qWh, *qBh, *qWout, *qBout;
    const float *y0, *dW;

    if (in_sizes[0] == 1) {
        y0    = (const float*)d_in[0];
        yWin  = (const float*)d_in[1];
        yBin  = (const float*)d_in[2];
        yWh   = (const float*)d_in[3];
        yBh   = (const float*)d_in[4];
        yWout = (const float*)d_in[5];
        yBout = (const float*)d_in[6];
        qWin  = (const float*)d_in[7];
        qBin  = (const float*)d_in[8];
        qWh   = (const float*)d_in[9];
        qBh   = (const float*)d_in[10];
        qWout = (const float*)d_in[11];
        qBout = (const float*)d_in[12];
        dW    = (const float*)d_in[13];
    } else {
        yWin  = (const float*)d_in[0];
        yBin  = (const float*)d_in[1];
        yWh   = (const float*)d_in[2];
        yBh   = (const float*)d_in[3];
        yWout = (const float*)d_in[4];
        yBout = (const float*)d_in[5];
        qWin  = (const float*)d_in[6];
        qBin  = (const float*)d_in[7];
        qWh   = (const float*)d_in[8];
        qBh   = (const float*)d_in[9];
        qWout = (const float*)d_in[10];
        qBout = (const float*)d_in[11];
        y0    = (const float*)d_in[12];
        dW    = (const float*)d_in[13];
    }

    cudaFuncSetAttribute(fbsnn_main, cudaFuncAttributeMaxDynamicSharedMemorySize,
                         SMEM_BYTES);

    fbsnn_main<<<NCTA, NTHR, SMEM_BYTES>>>(yWin, yBin, yWh, yBh, yWout, yBout,
                                           qWin, qBin, qWh, qBh, qWout, qBout,
                                           y0, dW);
    k_fin<<<1, NTHR>>>((float*)d_out);
}

// round 3
// speedup vs baseline: 1.0339x; 1.0339x over previous
#include <cuda_runtime.h>

#define DTV      0.02f
#define SQRT_DT  0.141421356237309515f
#define SIGMA    0.5f
#define NSTEP    50
#define BATCH    4096
#define PPC      32            // paths per CTA
#define NCTA     (BATCH / PPC) // 128
#define NTHR     128

typedef unsigned long long u64;

// ---- shared-memory layout (float offsets) ----
#define W_IN   0       // [2][64] = 128
#define B_IN   128     // 64
#define W_H    192     // [3][64][64] = 12288
#define B_H    12480   // [3][64] = 192
#define W_OUT  12672   // 64
#define B_OUT  12736   // 1 (+3 pad)
#define NET_SZ 12740
// activations: duplicated pairs {x,x}, [64 rows][32 u64], XOR-swizzled chunks
#define XBUF     4096
#define OFF_X    (2 * NET_SZ)
#define OFF_DX   (OFF_X   + XBUF)
#define OFF_XN   (OFF_DX  + XBUF)
#define OFF_DXN  (OFF_XN  + XBUF)
#define OFF_QX   (OFF_DXN + XBUF)
#define OFF_QXN  (OFF_QX  + XBUF)
#define OFF_YS   (OFF_QXN + XBUF)
#define OFF_HD   (OFF_YS  + 32)        // 96 floats: Y | dY | q heads
#define SMEM_FLOATS (OFF_HD + 96)
#define SMEM_BYTES  (SMEM_FLOATS * 4)

__device__ float g_part[NCTA];
__device__ int   g_count = 0;

__device__ __forceinline__ void cpf(float* d, const float* s, int n, int tid) {
    for (int i = tid; i < n; i += NTHR) d[i] = s[i];
}

__device__ __forceinline__ u64 fma2(u64 a, u64 b, u64 c) {
    u64 d;
    asm("fma.rn.f32x2 %0, %1, %2, %3;" : "=l"(d) : "l"(a), "l"(b), "l"(c));
    return d;
}
__device__ __forceinline__ u64 pk(float lo, float hi) {
    u64 r;
    asm("mov.b64 %0, {%1, %2};" : "=l"(r) : "f"(lo), "f"(hi));
    return r;
}
__device__ __forceinline__ void upk(u64 v, float& lo, float& hi) {
    asm("mov.b64 {%0, %1}, %2;" : "=f"(lo), "=f"(hi) : "l"(v));
}

// swizzled 16B-chunk index within a 64-row x 256B activation buffer
__device__ __forceinline__ int swz(int c, int r) { return c ^ ((r >> 2) & 15); }

// Fused hidden layer for BOTH nets on the same topology:
//  Y net with tangent:  Xn = sin(W_Y X + b_Y),  dXn = cos(.)*(W_Y dX)
//  q net value only:    QXn = sin(W_q QX + b_q)
__device__ __forceinline__ void fused_layer(
    const float* __restrict__ Wy, const float* __restrict__ by,
    const float* __restrict__ Wq, const float* __restrict__ bq,
    const float* __restrict__ X,  const float* __restrict__ dXb,
    const float* __restrict__ QX,
    float* __restrict__ Xn, float* __restrict__ dXn, float* __restrict__ QXn,
    int jg, int pg)
{
    const ulonglong2* WY2 = (const ulonglong2*)Wy;
    const ulonglong2* WQ2 = (const ulonglong2*)Wq;
    const ulonglong2* X2  = (const ulonglong2*)X;
    const ulonglong2* dX2 = (const ulonglong2*)dXb;
    const ulonglong2* QX2 = (const ulonglong2*)QX;

    const int j0 = jg * 4;

    u64 ah[2][4], ad[2][4], aq[2][4];
    {
        u64 by01 = pk(by[j0], by[j0 + 1]);
        u64 by23 = pk(by[j0 + 2], by[j0 + 3]);
        u64 bq01 = pk(bq[j0], bq[j0 + 1]);
        u64 bq23 = pk(bq[j0 + 2], bq[j0 + 3]);
#pragma unroll
        for (int p = 0; p < 4; p++) {
            ah[0][p] = by01; ah[1][p] = by23;
            aq[0][p] = bq01; aq[1][p] = bq23;
            ad[0][p] = 0ull; ad[1][p] = 0ull;
        }
    }

#pragma unroll 4
    for (int i = 0; i < 64; i++) {
        ulonglong2 wY = WY2[i * 16 + jg];
        ulonglong2 wQ = WQ2[i * 16 + jg];
        int c0 = swz(pg * 2, i);
        int c1 = swz(pg * 2 + 1, i);
        ulonglong2 xa = X2[i * 16 + c0];
        ulonglong2 xb = X2[i * 16 + c1];
        ulonglong2 da = dX2[i * 16 + c0];
        ulonglong2 db = dX2[i * 16 + c1];
        ulonglong2 qa = QX2[i * 16 + c0];
        ulonglong2 qb = QX2[i * 16 + c1];
        u64 xd[4] = {xa.x, xa.y, xb.x, xb.y};
        u64 dd[4] = {da.x, da.y, db.x, db.y};
        u64 qd[4] = {qa.x, qa.y, qb.x, qb.y};
#pragma unroll
        for (int p = 0; p < 4; p++) {
            ah[0][p] = fma2(wY.x, xd[p], ah[0][p]);
            ah[1][p] = fma2(wY.y, xd[p], ah[1][p]);
            ad[0][p] = fma2(wY.x, dd[p], ad[0][p]);
            ad[1][p] = fma2(wY.y, dd[p], ad[1][p]);
            aq[0][p] = fma2(wQ.x, qd[p], aq[0][p]);
            aq[1][p] = fma2(wQ.y, qd[p], aq[1][p]);
        }
    }

    float hv[4][4], dv[4][4], qv[4][4];
#pragma unroll
    for (int p = 0; p < 4; p++) {
        upk(ah[0][p], hv[0][p], hv[1][p]);
        upk(ah[1][p], hv[2][p], hv[3][p]);
        upk(ad[0][p], dv[0][p], dv[1][p]);
        upk(ad[1][p], dv[2][p], dv[3][p]);
        upk(aq[0][p], qv[0][p], qv[1][p]);
        upk(aq[1][p], qv[2][p], qv[3][p]);
    }

    ulonglong2* Xn2  = (ulonglong2*)Xn;
    ulonglong2* dXn2 = (ulonglong2*)dXn;
    ulonglong2* QXn2 = (ulonglong2*)QXn;
#pragma unroll
    for (int jj = 0; jj < 4; jj++) {
        int r = j0 + jj;
        int cc0 = swz(pg * 2, r);
        int cc1 = swz(pg * 2 + 1, r);
        float s[4], c[4], sq[4];
#pragma unroll
        for (int p = 0; p < 4; p++) {
            __sincosf(hv[jj][p], &s[p], &c[p]);
            sq[p] = __sinf(qv[jj][p]);
        }
        Xn2[r * 16 + cc0] = make_ulonglong2(pk(s[0], s[0]), pk(s[1], s[1]));
        Xn2[r * 16 + cc1] = make_ulonglong2(pk(s[2], s[2]), pk(s[3], s[3]));
        float d0 = c[0] * dv[jj][0], d1 = c[1] * dv[jj][1];
        float d2 = c[2] * dv[jj][2], d3 = c[3] * dv[jj][3];
        dXn2[r * 16 + cc0] = make_ulonglong2(pk(d0, d0), pk(d1, d1));
        dXn2[r * 16 + cc1] = make_ulonglong2(pk(d2, d2), pk(d3, d3));
        QXn2[r * 16 + cc0] = make_ulonglong2(pk(sq[0], sq[0]), pk(sq[1], sq[1]));
        QXn2[r * 16 + cc1] = make_ulonglong2(pk(sq[2], sq[2]), pk(sq[3], sq[3]));
    }
}

// Fused full-net evaluation at time tval on smem state ys[].
// Results land in sm[OFF_HD]: [0..31]=Y, [32..63]=dY, [64..95]=q. Ends synced.
__device__ __forceinline__ void eval_fused(float* sm, float tval,
                                           int jg, int pg, int tid)
{
    const float* netY = sm;
    const float* netQ = sm + NET_SZ;
    float* X   = sm + OFF_X;
    float* dXb = sm + OFF_DX;
    float* Xn  = sm + OFF_XN;
    float* dXn = sm + OFF_DXN;
    float* QX  = sm + OFF_QX;
    float* QXn = sm + OFF_QXN;
    const float* ys = sm + OFF_YS;

    const int j0 = jg * 4, p0 = pg * 4;

    // ---- fused input layer ----
    {
        ulonglong2* X2  = (ulonglong2*)X;
        ulonglong2* dX2 = (ulonglong2*)dXb;
        ulonglong2* QX2 = (ulonglong2*)QX;
        float yv[4] = {ys[p0], ys[p0 + 1], ys[p0 + 2], ys[p0 + 3]};
#pragma unroll
        for (int jj = 0; jj < 4; jj++) {
            int r = j0 + jj;
            float wtY = netY[W_IN + r], wyY = netY[W_IN + 64 + r];
            float tbY = fmaf(tval, wtY, netY[B_IN + r]);
            float wtQ = netQ[W_IN + r], wyQ = netQ[W_IN + 64 + r];
            float tbQ = fmaf(tval, wtQ, netQ[B_IN + r]);
            float s[4], c[4], sq[4];
#pragma unroll
            for (int p = 0; p < 4; p++) {
                __sincosf(fmaf(yv[p], wyY, tbY), &s[p], &c[p]);
                sq[p] = __sinf(fmaf(yv[p], wyQ, tbQ));
            }
            int cc0 = swz(pg * 2, r);
            int cc1 = swz(pg * 2 + 1, r);
            X2[r * 16 + cc0] = make_ulonglong2(pk(s[0], s[0]), pk(s[1], s[1]));
            X2[r * 16 + cc1] = make_ulonglong2(pk(s[2], s[2]), pk(s[3], s[3]));
            float d0 = c[0] * wyY, d1 = c[1] * wyY, d2 = c[2] * wyY, d3 = c[3] * wyY;
            dX2[r * 16 + cc0] = make_ulonglong2(pk(d0, d0), pk(d1, d1));
            dX2[r * 16 + cc1] = make_ulonglong2(pk(d2, d2), pk(d3, d3));
            QX2[r * 16 + cc0] = make_ulonglong2(pk(sq[0], sq[0]), pk(sq[1], sq[1]));
            QX2[r * 16 + cc1] = make_ulonglong2(pk(sq[2], sq[2]), pk(sq[3], sq[3]));
        }
    }
    __syncthreads();
    fused_layer(netY + W_H,        netY + B_H,       netQ + W_H,        netQ + B_H,
                X, dXb, QX, Xn, dXn, QXn, jg, pg);
    __syncthreads();
    fused_layer(netY + W_H + 4096, netY + B_H + 64,  netQ + W_H + 4096, netQ + B_H + 64,
                Xn, dXn, QXn, X, dXb, QX, jg, pg);
    __syncthreads();
    fused_layer(netY + W_H + 8192, netY + B_H + 128, netQ + W_H + 8192, netQ + B_H + 128,
                X, dXb, QX, Xn, dXn, QXn, jg, pg);
    __syncthreads();

    // ---- output heads: warp0 = Y value, warp1 = dY, warp2 = q ----
    const int wid = tid >> 5, lane = tid & 31;
    float* HD = sm + OFF_HD;
    if (wid < 3) {
        const float* src = (wid == 0) ? Xn : (wid == 1) ? dXn : QXn;
        const float* wv  = (wid == 2) ? (netQ + W_OUT) : (netY + W_OUT);
        float a0 = 0.0f, a1 = 0.0f, a2 = 0.0f, a3 = 0.0f;
        int p = lane;
#pragma unroll 8
        for (int i = 0; i < 64; i += 4) {
#pragma unroll
            for (int k = 0; k < 4; k++) {
                int ii = i + k;
                int ch = swz(p >> 1, ii);
                int off = ii * 64 + ch * 4 + (p & 1) * 2;
                float v = src[off] * wv[ii];
                if (k == 0) a0 += v; else if (k == 1) a1 += v;
                else if (k == 2) a2 += v; else a3 += v;
            }
        }
        float bias = (wid == 0) ? netY[B_OUT] : (wid == 2) ? netQ[B_OUT] : 0.0f;
        HD[wid * 32 + lane] = (a0 + a1) + (a2 + a3) + bias;
    }
    __syncthreads();
}

__global__ __launch_bounds__(NTHR, 1) void fbsnn_main(
    const float* __restrict__ yWin,  const float* __restrict__ yBin,
    const float* __restrict__ yWh,   const float* __restrict__ yBh,
    const float* __restrict__ yWout, const float* __restrict__ yBout,
    const float* __restrict__ qWin,  const float* __restrict__ qBin,
    const float* __restrict__ qWh,   const float* __restrict__ qBh,
    const float* __restrict__ qWout, const float* __restrict__ qBout,
    const float* __restrict__ y0,    const float* __restrict__ dW,
    float* __restrict__ out)
{
    extern __shared__ float sm[];
    const int tid = threadIdx.x;
    const int jg = tid & 15;
    const int pg = tid >> 4;

    // ---- stage all weights into smem once ----
    cpf(sm + W_IN,  yWin, 128,   tid);
    cpf(sm + B_IN,  yBin, 64,    tid);
    cpf(sm + W_H,   yWh,  12288, tid);
    cpf(sm + B_H,   yBh,  192,   tid);
    cpf(sm + W_OUT, yWout, 64,   tid);
    if (tid == 0) sm[B_OUT] = yBout[0];
    float* smq = sm + NET_SZ;
    cpf(smq + W_IN,  qWin, 128,   tid);
    cpf(smq + B_IN,  qBin, 64,    tid);
    cpf(smq + W_H,   qWh,  12288, tid);
    cpf(smq + B_H,   qBh,  192,   tid);
    cpf(smq + W_OUT, qWout, 64,   tid);
    if (tid == 0) smq[B_OUT] = qBout[0];
    if (tid < 32) sm[OFF_YS + tid] = y0[0];
    __syncthreads();

    float lossAcc = 0.0f, Ytilde = 0.0f;
    const int pbase = blockIdx.x * PPC;
    float* HD = sm + OFF_HD;

    // initial fused eval at t = 0: gives Y0, dY0, q0
    eval_fused(sm, 0.0f, jg, pg, tid);

    for (int n = 0; n < NSTEP; n++) {
        if (tid < 32) {
            float Yv  = HD[tid];
            float dYv = HD[32 + tid];
            float qv  = HD[64 + tid];
            float dwn = SQRT_DT * dW[n * BATCH + pbase + tid];
            Ytilde = Yv - qv * qv * DTV + SIGMA * dYv * dwn;
            sm[OFF_YS + tid] += qv * DTV + SIGMA * dwn;
        }
        __syncthreads();

        eval_fused(sm, (float)(n + 1) * DTV, jg, pg, tid);

        if (tid < 32) {
            float e = HD[tid] - Ytilde;
            lossAcc = fmaf(e, e, lossAcc);
        }
    }

    if (tid < 32) {
        float yN = sm[OFF_YS + tid];
        float e1 = HD[tid]      - yN * yN;   // terminal value residual
        float e2 = HD[32 + tid] - 2.0f * yN; // terminal gradient residual
        lossAcc = fmaf(e1, e1, fmaf(e2, e2, lossAcc));
#pragma unroll
        for (int o = 16; o > 0; o >>= 1)
            lossAcc += __shfl_down_sync(0xffffffffu, lossAcc, o);
        if (tid == 0) g_part[blockIdx.x] = lossAcc;
    }

    // ---- last-CTA deterministic reduction (single-launch design) ----
    if (tid == 0) {
        __threadfence();
        int old = atomicAdd(&g_count, 1);
        if (old == NCTA - 1) {
            __threadfence();
            float acc = 0.0f;
#pragma unroll 8
            for (int i = 0; i < NCTA; i++) acc += g_part[i];
            out[0] = acc * (1.0f / (float)BATCH);
            g_count = 0;
        }
    }
}

extern "C" void kernel_launch(void* const* d_in, const int* in_sizes, int n_in,
                              void* d_out, int out_size)
{
    const float *yWin, *yBin, *yWh, *yBh, *yWout, *yBout;
    const float *qWin, *qBin, *qWh, *qBh, *qWout, *qBout;
    const float *y0, *dW;

    if (in_sizes[0] == 1) {
        y0    = (const float*)d_in[0];
        yWin  = (const float*)d_in[1];
        yBin  = (const float*)d_in[2];
        yWh   = (const float*)d_in[3];
        yBh   = (const float*)d_in[4];
        yWout = (const float*)d_in[5];
        yBout = (const float*)d_in[6];
        qWin  = (const float*)d_in[7];
        qBin  = (const float*)d_in[8];
        qWh   = (const float*)d_in[9];
        qBh   = (const float*)d_in[10];
        qWout = (const float*)d_in[11];
        qBout = (const float*)d_in[12];
        dW    = (const float*)d_in[13];
    } else {
        yWin  = (const float*)d_in[0];
        yBin  = (const float*)d_in[1];
        yWh   = (const float*)d_in[2];
        yBh   = (const float*)d_in[3];
        yWout = (const float*)d_in[4];
        yBout = (const float*)d_in[5];
        qWin  = (const float*)d_in[6];
        qBin  = (const float*)d_in[7];
        qWh   = (const float*)d_in[8];
        qBh   = (const float*)d_in[9];
        qWout = (const float*)d_in[10];
        qBout = (const float*)d_in[11];
        y0    = (const float*)d_in[12];
        dW    = (const float*)d_in[13];
    }

    cudaFuncSetAttribute(fbsnn_main, cudaFuncAttributeMaxDynamicSharedMemorySize,
                         SMEM_BYTES);

    fbsnn_main<<<NCTA, NTHR, SMEM_BYTES>>>(yWin, yBin, yWh, yBh, yWout, yBout,
                                           qWin, qBin, qWh, qBh, qWout, qBout,
                                           y0, dW, (float*)d_out);
}

// round 4
// speedup vs baseline: 1.0764x; 1.0411x over previous
#include <cuda_runtime.h>

#define DTV      0.02f
#define SQRT_DT  0.141421356237309515f
#define SIGMA    0.5f
#define NSTEP    50
#define BATCH    4096
#define PPC      32            // paths per CTA
#define NCTA     (BATCH / PPC) // 128
#define NTHR     256

typedef unsigned long long u64;

// ---- shared-memory layout (float offsets) ----
#define W_IN   0       // [2][64] = 128
#define B_IN   128     // 64
#define W_H    192     // [3][64][64] = 12288
#define B_H    12480   // [3][64] = 192
#define W_OUT  12672   // 64
#define B_OUT  12736   // 1 (+3 pad)
#define NET_SZ 12740
// activations: duplicated pairs {x,x}, [64 rows][32 u64], XOR-swizzled chunks
#define XBUF     4096
#define OFF_X    (2 * NET_SZ)
#define OFF_DX   (OFF_X   + XBUF)
#define OFF_XN   (OFF_DX  + XBUF)
#define OFF_DXN  (OFF_XN  + XBUF)
#define OFF_QX   (OFF_DXN + XBUF)
#define OFF_QXN  (OFF_QX  + XBUF)
// K-split partial exchange buffers: [12][128] u64 each
#define OFF_PX   (OFF_QXN + XBUF)     // A's pair1 partials (3072 floats)
#define OFF_PY   (OFF_PX  + 3072)     // B's pair0 partials
#define OFF_YS   (OFF_PY  + 3072)
#define OFF_HD2  (OFF_YS  + 32)       // [2][96] head partials
#define OFF_HD   (OFF_HD2 + 192)      // 96 floats: Y | dY | q
#define SMEM_FLOATS (OFF_HD + 96)
#define SMEM_BYTES  (SMEM_FLOATS * 4)

__device__ float g_part[NCTA];
__device__ int   g_count = 0;

__device__ __forceinline__ void cpf(float* d, const float* s, int n, int tid) {
    for (int i = tid; i < n; i += NTHR) d[i] = s[i];
}

__device__ __forceinline__ u64 fma2(u64 a, u64 b, u64 c) {
    u64 d;
    asm("fma.rn.f32x2 %0, %1, %2, %3;" : "=l"(d) : "l"(a), "l"(b), "l"(c));
    return d;
}
__device__ __forceinline__ u64 add2(u64 a, u64 b) {
    u64 d;
    asm("add.rn.f32x2 %0, %1, %2;" : "=l"(d) : "l"(a), "l"(b));
    return d;
}
__device__ __forceinline__ u64 pk(float lo, float hi) {
    u64 r;
    asm("mov.b64 %0, {%1, %2};" : "=l"(r) : "f"(lo), "f"(hi));
    return r;
}
__device__ __forceinline__ void upk(u64 v, float& lo, float& hi) {
    asm("mov.b64 {%0, %1}, %2;" : "=f"(lo), "=f"(hi) : "l"(v));
}

// swizzled 16B-chunk index within a 64-row x 256B activation buffer
__device__ __forceinline__ int swz(int c, int r) { return c ^ ((r >> 2) & 15); }

// store 2 rows (rbase, rbase+1) of sin/dsin/q activations from one packed pair
__device__ __forceinline__ void epilogue_rows(
    float* __restrict__ Xn, float* __restrict__ dXn, float* __restrict__ QXn,
    int rbase, int pg, u64 ahp[4], u64 adp[4], u64 aqp[4])
{
    float h0[4], h1[4], d0v[4], d1v[4], q0[4], q1[4];
#pragma unroll
    for (int p = 0; p < 4; p++) {
        upk(ahp[p], h0[p], h1[p]);
        upk(adp[p], d0v[p], d1v[p]);
        upk(aqp[p], q0[p], q1[p]);
    }
    ulonglong2* Xn2  = (ulonglong2*)Xn;
    ulonglong2* dXn2 = (ulonglong2*)dXn;
    ulonglong2* QXn2 = (ulonglong2*)QXn;
#pragma unroll
    for (int rr = 0; rr < 2; rr++) {
        int r = rbase + rr;
        const float* hv = rr ? h1 : h0;
        const float* dv = rr ? d1v : d0v;
        const float* qv = rr ? q1 : q0;
        float s[4], c[4], sq[4];
#pragma unroll
        for (int p = 0; p < 4; p++) {
            __sincosf(hv[p], &s[p], &c[p]);
            sq[p] = __sinf(qv[p]);
        }
        int cc0 = swz(pg * 2, r);
        int cc1 = swz(pg * 2 + 1, r);
        Xn2[r * 16 + cc0] = make_ulonglong2(pk(s[0], s[0]), pk(s[1], s[1]));
        Xn2[r * 16 + cc1] = make_ulonglong2(pk(s[2], s[2]), pk(s[3], s[3]));
        float e0 = c[0] * dv[0], e1 = c[1] * dv[1];
        float e2 = c[2] * dv[2], e3 = c[3] * dv[3];
        dXn2[r * 16 + cc0] = make_ulonglong2(pk(e0, e0), pk(e1, e1));
        dXn2[r * 16 + cc1] = make_ulonglong2(pk(e2, e2), pk(e3, e3));
        QXn2[r * 16 + cc0] = make_ulonglong2(pk(sq[0], sq[0]), pk(sq[1], sq[1]));
        QXn2[r * 16 + cc1] = make_ulonglong2(pk(sq[2], sq[2]), pk(sq[3], sq[3]));
    }
}

// Fused hidden layer, K-split across the two thread halves.
// half A (tid<128): i in [0,32);  half B: i in [32,64).
// Exchange packed partials through smem, each half finishes 2 of its 4 rows.
__device__ __forceinline__ void fused_layer(
    float* __restrict__ sm,
    const float* __restrict__ Wy, const float* __restrict__ by,
    const float* __restrict__ Wq, const float* __restrict__ bq,
    const float* __restrict__ X,  const float* __restrict__ dXb,
    const float* __restrict__ QX,
    float* __restrict__ Xn, float* __restrict__ dXn, float* __restrict__ QXn,
    int jg, int pg, int half, int ht)
{
    const ulonglong2* WY2 = (const ulonglong2*)Wy;
    const ulonglong2* WQ2 = (const ulonglong2*)Wq;
    const ulonglong2* X2  = (const ulonglong2*)X;
    const ulonglong2* dX2 = (const ulonglong2*)dXb;
    const ulonglong2* QX2 = (const ulonglong2*)QX;

    const int j0 = jg * 4;
    const int ib = half * 32;

    u64 ah[2][4], ad[2][4], aq[2][4];
    {
        u64 by01 = pk(by[j0], by[j0 + 1]);
        u64 by23 = pk(by[j0 + 2], by[j0 + 3]);
        u64 bq01 = pk(bq[j0], bq[j0 + 1]);
        u64 bq23 = pk(bq[j0 + 2], bq[j0 + 3]);
#pragma unroll
        for (int p = 0; p < 4; p++) {
            ah[0][p] = half ? 0ull : by01;
            ah[1][p] = half ? by23 : 0ull;
            aq[0][p] = half ? 0ull : bq01;
            aq[1][p] = half ? bq23 : 0ull;
            ad[0][p] = 0ull; ad[1][p] = 0ull;
        }
    }

#pragma unroll 4
    for (int k = 0; k < 32; k++) {
        int i = ib + k;
        ulonglong2 wY = WY2[i * 16 + jg];
        ulonglong2 wQ = WQ2[i * 16 + jg];
        int c0 = swz(pg * 2, i);
        int c1 = swz(pg * 2 + 1, i);
        ulonglong2 xa = X2[i * 16 + c0];
        ulonglong2 xb = X2[i * 16 + c1];
        ulonglong2 da = dX2[i * 16 + c0];
        ulonglong2 db = dX2[i * 16 + c1];
        ulonglong2 qa = QX2[i * 16 + c0];
        ulonglong2 qb = QX2[i * 16 + c1];
        u64 xd[4] = {xa.x, xa.y, xb.x, xb.y};
        u64 dd[4] = {da.x, da.y, db.x, db.y};
        u64 qd[4] = {qa.x, qa.y, qb.x, qb.y};
#pragma unroll
        for (int p = 0; p < 4; p++) {
            ah[0][p] = fma2(wY.x, xd[p], ah[0][p]);
            ah[1][p] = fma2(wY.y, xd[p], ah[1][p]);
            ad[0][p] = fma2(wY.x, dd[p], ad[0][p]);
            ad[1][p] = fma2(wY.y, dd[p], ad[1][p]);
            aq[0][p] = fma2(wQ.x, qd[p], aq[0][p]);
            aq[1][p] = fma2(wQ.y, qd[p], aq[1][p]);
        }
    }

    // ---- partial exchange: A gives pair1, B gives pair0 ----
    u64* PX = (u64*)(sm + OFF_PX);   // written by A
    u64* PY = (u64*)(sm + OFF_PY);   // written by B
    if (half == 0) {
#pragma unroll
        for (int p = 0; p < 4; p++) {
            PX[(0 + p) * 128 + ht] = ah[1][p];
            PX[(4 + p) * 128 + ht] = ad[1][p];
            PX[(8 + p) * 128 + ht] = aq[1][p];
        }
    } else {
#pragma unroll
        for (int p = 0; p < 4; p++) {
            PY[(0 + p) * 128 + ht] = ah[0][p];
            PY[(4 + p) * 128 + ht] = ad[0][p];
            PY[(8 + p) * 128 + ht] = aq[0][p];
        }
    }
    __syncthreads();
    if (half == 0) {
#pragma unroll
        for (int p = 0; p < 4; p++) {
            ah[0][p] = add2(ah[0][p], PY[(0 + p) * 128 + ht]);
            ad[0][p] = add2(ad[0][p], PY[(4 + p) * 128 + ht]);
            aq[0][p] = add2(aq[0][p], PY[(8 + p) * 128 + ht]);
        }
        epilogue_rows(Xn, dXn, QXn, j0, pg, ah[0], ad[0], aq[0]);
    } else {
#pragma unroll
        for (int p = 0; p < 4; p++) {
            ah[1][p] = add2(ah[1][p], PX[(0 + p) * 128 + ht]);
            ad[1][p] = add2(ad[1][p], PX[(4 + p) * 128 + ht]);
            aq[1][p] = add2(aq[1][p], PX[(8 + p) * 128 + ht]);
        }
        epilogue_rows(Xn, dXn, QXn, j0 + 2, pg, ah[1], ad[1], aq[1]);
    }
    __syncthreads();
}

// Fused full-net evaluation; results in sm[OFF_HD]: Y | dY | q. Ends synced.
__device__ __forceinline__ void eval_fused(float* sm, float tval,
                                           int jg, int pg, int half, int ht,
                                           int tid)
{
    const float* netY = sm;
    const float* netQ = sm + NET_SZ;
    float* X   = sm + OFF_X;
    float* dXb = sm + OFF_DX;
    float* Xn  = sm + OFF_XN;
    float* dXn = sm + OFF_DXN;
    float* QX  = sm + OFF_QX;
    float* QXn = sm + OFF_QXN;
    const float* ys = sm + OFF_YS;

    const int j0 = jg * 4, p0 = pg * 4;

    // ---- input layer: A does rows j0,j0+1; B does j0+2,j0+3 ----
    {
        ulonglong2* X2  = (ulonglong2*)X;
        ulonglong2* dX2 = (ulonglong2*)dXb;
        ulonglong2* QX2 = (ulonglong2*)QX;
        float yv[4] = {ys[p0], ys[p0 + 1], ys[p0 + 2], ys[p0 + 3]};
#pragma unroll
        for (int jj = 0; jj < 2; jj++) {
            int r = j0 + half * 2 + jj;
            float wtY = netY[W_IN + r], wyY = netY[W_IN + 64 + r];
            float tbY = fmaf(tval, wtY, netY[B_IN + r]);
            float wtQ = netQ[W_IN + r], wyQ = netQ[W_IN + 64 + r];
            float tbQ = fmaf(tval, wtQ, netQ[B_IN + r]);
            float s[4], c[4], sq[4];
#pragma unroll
            for (int p = 0; p < 4; p++) {
                __sincosf(fmaf(yv[p], wyY, tbY), &s[p], &c[p]);
                sq[p] = __sinf(fmaf(yv[p], wyQ, tbQ));
            }
            int cc0 = swz(pg * 2, r);
            int cc1 = swz(pg * 2 + 1, r);
            X2[r * 16 + cc0] = make_ulonglong2(pk(s[0], s[0]), pk(s[1], s[1]));
            X2[r * 16 + cc1] = make_ulonglong2(pk(s[2], s[2]), pk(s[3], s[3]));
            float d0 = c[0] * wyY, d1 = c[1] * wyY, d2 = c[2] * wyY, d3 = c[3] * wyY;
            dX2[r * 16 + cc0] = make_ulonglong2(pk(d0, d0), pk(d1, d1));
            dX2[r * 16 + cc1] = make_ulonglong2(pk(d2, d2), pk(d3, d3));
            QX2[r * 16 + cc0] = make_ulonglong2(pk(sq[0], sq[0]), pk(sq[1], sq[1]));
            QX2[r * 16 + cc1] = make_ulonglong2(pk(sq[2], sq[2]), pk(sq[3], sq[3]));
        }
    }
    __syncthreads();
    fused_layer(sm, netY + W_H,        netY + B_H,       netQ + W_H,        netQ + B_H,
                X, dXb, QX, Xn, dXn, QXn, jg, pg, half, ht);
    fused_layer(sm, netY + W_H + 4096, netY + B_H + 64,  netQ + W_H + 4096, netQ + B_H + 64,
                Xn, dXn, QXn, X, dXb, QX, jg, pg, half, ht);
    fused_layer(sm, netY + W_H + 8192, netY + B_H + 128, netQ + W_H + 8192, netQ + B_H + 128,
                X, dXb, QX, Xn, dXn, QXn, jg, pg, half, ht);

    // ---- output heads, i-split: A warps 0-2 do i<32, B warps 4-6 do i>=32 ----
    const int wid = tid >> 5, lane = tid & 31;
    float* HD2 = sm + OFF_HD2;
    float* HD  = sm + OFF_HD;
    int hw = wid & 3;
    if (hw < 3) {
        const float* src = (hw == 0) ? Xn : (hw == 1) ? dXn : QXn;
        const float* wv  = (hw == 2) ? (netQ + W_OUT) : (netY + W_OUT);
        int i0 = half * 32;
        float a0 = 0.0f, a1 = 0.0f, a2 = 0.0f, a3 = 0.0f;
        int p = lane;
#pragma unroll 4
        for (int i = 0; i < 32; i += 4) {
#pragma unroll
            for (int k = 0; k < 4; k++) {
                int ii = i0 + i + k;
                int ch = swz(p >> 1, ii);
                int off = ii * 64 + ch * 4 + (p & 1) * 2;
                float v = src[off] * wv[ii];
                if (k == 0) a0 += v; else if (k == 1) a1 += v;
                else if (k == 2) a2 += v; else a3 += v;
            }
        }
        HD2[half * 96 + hw * 32 + lane] = (a0 + a1) + (a2 + a3);
    }
    __syncthreads();
    if (tid < 96) {
        int head = tid >> 5;
        float bias = (head == 0) ? netY[B_OUT] : (head == 2) ? netQ[B_OUT] : 0.0f;
        HD[tid] = HD2[tid] + HD2[96 + tid] + bias;
    }
    __syncthreads();
}

__global__ __launch_bounds__(NTHR, 1) void fbsnn_main(
    const float* __restrict__ yWin,  const float* __restrict__ yBin,
    const float* __restrict__ yWh,   const float* __restrict__ yBh,
    const float* __restrict__ yWout, const float* __restrict__ yBout,
    const float* __restrict__ qWin,  const float* __restrict__ qBin,
    const float* __restrict__ qWh,   const float* __restrict__ qBh,
    const float* __restrict__ qWout, const float* __restrict__ qBout,
    const float* __restrict__ y0,    const float* __restrict__ dW,
    float* __restrict__ out)
{
    extern __shared__ float sm[];
    const int tid = threadIdx.x;
    const int half = tid >> 7;
    const int ht = tid & 127;
    const int jg = ht & 15;
    const int pg = ht >> 4;

    // ---- stage all weights into smem once ----
    cpf(sm + W_IN,  yWin, 128,   tid);
    cpf(sm + B_IN,  yBin, 64,    tid);
    cpf(sm + W_H,   yWh,  12288, tid);
    cpf(sm + B_H,   yBh,  192,   tid);
    cpf(sm + W_OUT, yWout, 64,   tid);
    if (tid == 0) sm[B_OUT] = yBout[0];
    float* smq = sm + NET_SZ;
    cpf(smq + W_IN,  qWin, 128,   tid);
    cpf(smq + B_IN,  qBin, 64,    tid);
    cpf(smq + W_H,   qWh,  12288, tid);
    cpf(smq + B_H,   qBh,  192,   tid);
    cpf(smq + W_OUT, qWout, 64,   tid);
    if (tid == 0) smq[B_OUT] = qBout[0];
    if (tid < 32) sm[OFF_YS + tid] = y0[0];
    __syncthreads();

    float lossAcc = 0.0f, Ytilde = 0.0f;
    const int pbase = blockIdx.x * PPC;
    float* HD = sm + OFF_HD;

    // initial fused eval at t = 0: gives Y0, dY0, q0
    eval_fused(sm, 0.0f, jg, pg, half, ht, tid);

    for (int n = 0; n < NSTEP; n++) {
        if (tid < 32) {
            float Yv  = HD[tid];
            float dYv = HD[32 + tid];
            float qv  = HD[64 + tid];
            float dwn = SQRT_DT * dW[n * BATCH + pbase + tid];
            Ytilde = Yv - qv * qv * DTV + SIGMA * dYv * dwn;
            sm[OFF_YS + tid] += qv * DTV + SIGMA * dwn;
        }
        __syncthreads();

        eval_fused(sm, (float)(n + 1) * DTV, jg, pg, half, ht, tid);

        if (tid < 32) {
            float e = HD[tid] - Ytilde;
            lossAcc = fmaf(e, e, lossAcc);
        }
    }

    if (tid < 32) {
        float yN = sm[OFF_YS + tid];
        float e1 = HD[tid]      - yN * yN;   // terminal value residual
        float e2 = HD[32 + tid] - 2.0f * yN; // terminal gradient residual
        lossAcc = fmaf(e1, e1, fmaf(e2, e2, lossAcc));
#pragma unroll
        for (int o = 16; o > 0; o >>= 1)
            lossAcc += __shfl_down_sync(0xffffffffu, lossAcc, o);
        if (tid == 0) g_part[blockIdx.x] = lossAcc;
    }

    // ---- last-CTA deterministic reduction (single-launch design) ----
    if (tid == 0) {
        __threadfence();
        int old = atomicAdd(&g_count, 1);
        if (old == NCTA - 1) {
            __threadfence();
            float acc = 0.0f;
#pragma unroll 8
            for (int i = 0; i < NCTA; i++) acc += g_part[i];
            out[0] = acc * (1.0f / (float)BATCH);
            g_count = 0;
        }
    }
}

extern "C" void kernel_launch(void* const* d_in, const int* in_sizes, int n_in,
                              void* d_out, int out_size)
{
    const float *yWin, *yBin, *yWh, *yBh, *yWout, *yBout;
    const float *qWin, *qBin, *qWh, *qBh, *qWout, *qBout;
    const float *y0, *dW;

    if (in_sizes[0] == 1) {
        y0    = (const float*)d_in[0];
        yWin  = (const float*)d_in[1];
        yBin  = (const float*)d_in[2];
        yWh   = (const float*)d_in[3];
        yBh   = (const float*)d_in[4];
        yWout = (const float*)d_in[5];
        yBout = (const float*)d_in[6];
        qWin  = (const float*)d_in[7];
        qBin  = (const float*)d_in[8];
        qWh   = (const float*)d_in[9];
        qBh   = (const float*)d_in[10];
        qWout = (const float*)d_in[11];
        qBout = (const float*)d_in[12];
        dW    = (const float*)d_in[13];
    } else {
        yWin  = (const float*)d_in[0];
        yBin  = (const float*)d_in[1];
        yWh   = (const float*)d_in[2];
        yBh   = (const float*)d_in[3];
        yWout = (const float*)d_in[4];
        yBout = (const float*)d_in[5];
        qWin  = (const float*)d_in[6];
        qBin  = (const float*)d_in[7];
        qWh   = (const float*)d_in[8];
        qBh   = (const float*)d_in[9];
        qWout = (const float*)d_in[10];
        qBout = (const float*)d_in[11];
        y0    = (const float*)d_in[12];
        dW    = (const float*)d_in[13];
    }

    cudaFuncSetAttribute(fbsnn_main, cudaFuncAttributeMaxDynamicSharedMemorySize,
                         SMEM_BYTES);

    fbsnn_main<<<NCTA, NTHR, SMEM_BYTES>>>(yWin, yBin, yWh, yBh, yWout, yBout,
                                           qWin, qBin, qWh, qBh, qWout, qBout,
                                           y0, dW, (float*)d_out);
}